// round 14
// baseline (speedup 1.0000x reference)
#include <cuda_runtime.h>

#define NB 1024    // batch rows
#define NL 512     // labels per row
#define NT 128     // threads per block (one block per row)
#define NW 4       // warps per block
#define KB 256     // histogram bins
#define HB 128     // bins per half-scan
#define LOV (-8.0f)
#define BW  (0.0625f)    // 1/16
#define INVW (16.0f)
#define FULL 0xffffffffu
#define FXS 1073741824.0   // 2^30 fixed-point scale

__device__ unsigned long long g_acc[32];   // fixed-point partial sums (32 slots)
__device__ int g_cnt1[32];                 // level-1 counters (32 blocks each)
__device__ int g_cnt0 = 0;                 // level-0 counter (32 slots)

__inline__ __device__ float warpSum(float v) {
#pragma unroll
    for (int o = 16; o; o >>= 1) v += __shfl_xor_sync(FULL, v, o);
    return v;
}

__global__ __launch_bounds__(NT) void row_kernel(const float* __restrict__ outp,
                                                 const int* __restrict__ tgt,
                                                 float* __restrict__ out) {
    __shared__ __align__(16) int    hcnt[KB];    // positive-count histogram
    __shared__ __align__(16) float2 SP[KB];      // per-half inclusive prefix (count, wsum)
    __shared__ float2 sHalf[2];                  // per-half totals (C, W)
    __shared__ float s0[NW], s1[NW], s2[NW];

    const int row  = blockIdx.x;
    const int tid  = threadIdx.x;
    const int lane = tid & 31;
    const int wid  = tid >> 5;

    // ---- issue global loads FIRST (latency hides behind zero + barrier) ----
    const float4 ov = reinterpret_cast<const float4*>(outp + row * NL)[tid];
    const int4   tv = reinterpret_cast<const int4*>(tgt  + row * NL)[tid];

    // ---- zero histogram (128 threads x int2 = 256 bins) ----
    reinterpret_cast<int2*>(hcnt)[tid] = make_int2(0, 0);
    __syncthreads();                                   // bar0

    // ---- classify, calib sums, histogram atomics ----
    float vv[4] = {ov.x, ov.y, ov.z, ov.w};
    int   tt[4] = {tv.x, tv.y, tv.z, tv.w};
    unsigned negmask = 0;
    float pos_sum = 0.f, neg_sum = 0.f;
#pragma unroll
    for (int k = 0; k < 4; k++) {
        float v = vv[k];
        if (tt[k] != 0) {
            pos_sum += fmaxf(1.f - v, 0.f);
            int b = min(max(__float2int_rd((v - LOV) * INVW), 0), KB - 1);
            atomicAdd(&hcnt[b], 1);
        } else {
            neg_sum += fmaxf(1.f + v, 0.f);
            negmask |= 1u << k;
        }
    }
    __syncthreads();                                   // bar1

    // ---- concurrent half-scans: warp r scans bins [r*128, r*128+128) ----
    if (wid < 2) {
        const int r = wid;
        int4 a = reinterpret_cast<const int4*>(hcnt)[r * 32 + lane];  // 4 bins/lane
        int cb[4] = {a.x, a.y, a.z, a.w};
        const int b0 = r * HB + lane * 4;
        const float ctr0 = LOV + ((float)b0 + 0.5f) * BW;
        float rc = 0.f, rw = 0.f;
#pragma unroll
        for (int i = 0; i < 4; i++) {
            float f = (float)cb[i];
            rc += f;
            rw = fmaf(f, ctr0 + (float)i * BW, rw);
        }
        float sc = rc, sw = rw;                         // inclusive scan of lane totals
#pragma unroll
        for (int o = 1; o < 32; o <<= 1) {
            float tc = __shfl_up_sync(FULL, sc, o);
            float tw = __shfl_up_sync(FULL, sw, o);
            if (lane >= o) { sc += tc; sw += tw; }
        }
        float ac = sc - rc, aw = sw - rw;               // exclusive prefix within half
#pragma unroll
        for (int i = 0; i < 4; i++) {
            float f = (float)cb[i];
            ac += f;
            aw = fmaf(f, ctr0 + (float)i * BW, aw);
            SP[b0 + i] = make_float2(ac, aw);
        }
        if (lane == 31) sHalf[r] = make_float2(sc, sw); // half totals
    }
    __syncthreads();                                   // bar2

    // ---- per-negative O(1) lookup: sum relu(cc - p) ~= cc*cntBelow - wsumBelow ----
    const float2 h0 = sHalf[0];                        // broadcast
    float hacc = 0.f;
#pragma unroll
    for (int k = 0; k < 4; k++) {
        if (negmask & (1u << k)) {
            float cc = 1.f + vv[k];
            int m = min(max(__float2int_rd((cc - LOV) * INVW + 0.5f), 0), KB);
            if (m > 0) {
                float2 pw = SP[m - 1];
                float cA = pw.x, wA = pw.y;
                if (m > HB) { cA += h0.x; wA += h0.y; }
                hacc = fmaf(cc, cA, hacc - wA);
            }
        }
    }

    // ---- block reduce ----
    float r0 = warpSum(hacc);
    float r1 = warpSum(pos_sum);
    float r2 = warpSum(neg_sum);
    if (lane == 0) { s0[wid] = r0; s1[wid] = r1; s2[wid] = r2; }
    __syncthreads();                                   // bar3

    // ---- tid0 epilogue: fixed-point deterministic accumulation, no tail reload ----
    if (tid == 0) {
        float ps = 0.f, qs = 0.f, ns = 0.f;
#pragma unroll
        for (int w = 0; w < NW; w++) { ps += s0[w]; qs += s1[w]; ns += s2[w]; }
        int n_p = (int)(sHalf[0].x + sHalf[1].x);      // exact integer in fp32
        int n_n = NL - n_p;
        float pos_calib = (n_p > 0) ? qs / (float)n_p : 0.f;
        float neg_calib = (n_n > 0) ? ns / (float)n_n : 0.f;
        long long denom = (long long)n_p * (long long)n_n;
        float hinge;
        if (denom > 0)      hinge = ps / (float)denom;
        else if (n_p > 0)   hinge = pos_calib;
        else if (n_n > 0)   hinge = neg_calib;
        else                hinge = 1.f;
        float v = hinge + neg_calib + pos_calib;       // v >= 0 always

        const int slot = row & 31;
        unsigned long long fx =
            (unsigned long long)__double2ll_rn((double)v * FXS);
        atomicAdd(&g_acc[slot], fx);                   // order-independent (integer)
        __threadfence();                               // acc visible before counter
        if (atomicAdd(&g_cnt1[slot], 1) == 31) {       // last of this slot's 32 blocks
            if (atomicAdd(&g_cnt0, 1) == 31) {         // globally last block
                __threadfence();                       // acquire all slot adds
                unsigned long long total = 0;
#pragma unroll
                for (int i = 0; i < 32; i++) {
                    total += g_acc[i];
                    g_acc[i] = 0;                      // reset for next graph replay
                    g_cnt1[i] = 0;
                }
                g_cnt0 = 0;
                out[0] = (float)((double)total / FXS / (double)NB);
            }
        }
    }
}

extern "C" void kernel_launch(void* const* d_in, const int* in_sizes, int n_in,
                              void* d_out, int out_size) {
    const float* outputs = (const float*)d_in[0];
    const int*   targets = (const int*)d_in[1];
    row_kernel<<<NB, NT>>>(outputs, targets, (float*)d_out);
}

// round 16
// speedup vs baseline: 1.6761x; 1.6761x over previous
#include <cuda_runtime.h>

#define NB 1024    // batch rows
#define NL 512     // labels per row
#define NT 128     // threads per block (one block per row)
#define NW 4       // warps per block
#define KB 256     // histogram bins
#define HB 128     // bins per half-scan
#define LOV (-8.0f)
#define BW  (0.0625f)    // 1/16
#define INVW (16.0f)
#define FULL 0xffffffffu

__device__ float g_row[NB];
__device__ int   g_cnt1[32];   // level-1 counters (32 blocks each)
__device__ int   g_cnt0 = 0;   // level-0 counter (32 slots)

__inline__ __device__ float warpSum(float v) {
#pragma unroll
    for (int o = 16; o; o >>= 1) v += __shfl_xor_sync(FULL, v, o);
    return v;
}

__global__ __launch_bounds__(NT) void row_kernel(const float* __restrict__ outp,
                                                 const int* __restrict__ tgt,
                                                 float* __restrict__ out) {
    __shared__ __align__(16) int    hcnt[KB];    // positive-count histogram
    __shared__ __align__(16) float2 SP[KB];      // per-half inclusive prefix (count, wsum)
    __shared__ float2 sHalf[2];                  // per-half totals (C, W)
    __shared__ float s0[NW], s1[NW], s2[NW];

    const int row  = blockIdx.x;
    const int tid  = threadIdx.x;
    const int lane = tid & 31;
    const int wid  = tid >> 5;

    // ---- issue global loads FIRST (latency hides behind zero + barrier) ----
    const float4 ov = reinterpret_cast<const float4*>(outp + row * NL)[tid];
    const int4   tv = reinterpret_cast<const int4*>(tgt  + row * NL)[tid];

    // ---- zero histogram (128 threads x int2 = 256 bins) ----
    reinterpret_cast<int2*>(hcnt)[tid] = make_int2(0, 0);
    __syncthreads();                                   // bar0

    // ---- classify, calib sums, histogram atomics ----
    float vv[4] = {ov.x, ov.y, ov.z, ov.w};
    int   tt[4] = {tv.x, tv.y, tv.z, tv.w};
    unsigned negmask = 0;
    float pos_sum = 0.f, neg_sum = 0.f;
#pragma unroll
    for (int k = 0; k < 4; k++) {
        float v = vv[k];
        if (tt[k] != 0) {
            pos_sum += fmaxf(1.f - v, 0.f);
            int b = min(max(__float2int_rd((v - LOV) * INVW), 0), KB - 1);
            atomicAdd(&hcnt[b], 1);
        } else {
            neg_sum += fmaxf(1.f + v, 0.f);
            negmask |= 1u << k;
        }
    }
    __syncthreads();                                   // bar1

    // ---- concurrent half-scans: warp r scans bins [r*128, r*128+128) ----
    if (wid < 2) {
        const int r = wid;
        int4 a = reinterpret_cast<const int4*>(hcnt)[r * 32 + lane];  // 4 bins/lane
        int cb[4] = {a.x, a.y, a.z, a.w};
        const int b0 = r * HB + lane * 4;
        const float ctr0 = LOV + ((float)b0 + 0.5f) * BW;
        float rc = 0.f, rw = 0.f;
#pragma unroll
        for (int i = 0; i < 4; i++) {
            float f = (float)cb[i];
            rc += f;
            rw = fmaf(f, ctr0 + (float)i * BW, rw);
        }
        float sc = rc, sw = rw;                         // inclusive scan of lane totals
#pragma unroll
        for (int o = 1; o < 32; o <<= 1) {
            float tc = __shfl_up_sync(FULL, sc, o);
            float tw = __shfl_up_sync(FULL, sw, o);
            if (lane >= o) { sc += tc; sw += tw; }
        }
        float ac = sc - rc, aw = sw - rw;               // exclusive prefix within half
#pragma unroll
        for (int i = 0; i < 4; i++) {
            float f = (float)cb[i];
            ac += f;
            aw = fmaf(f, ctr0 + (float)i * BW, aw);
            SP[b0 + i] = make_float2(ac, aw);
        }
        if (lane == 31) sHalf[r] = make_float2(sc, sw); // half totals
    }
    __syncthreads();                                   // bar2

    // ---- per-negative O(1) lookup: sum relu(cc - p) ~= cc*cntBelow - wsumBelow ----
    const float2 h0 = sHalf[0];                        // broadcast
    float hacc = 0.f;
#pragma unroll
    for (int k = 0; k < 4; k++) {
        if (negmask & (1u << k)) {
            float cc = 1.f + vv[k];
            int m = min(max(__float2int_rd((cc - LOV) * INVW + 0.5f), 0), KB);
            if (m > 0) {
                float2 pw = SP[m - 1];
                float cA = pw.x, wA = pw.y;
                if (m > HB) { cA += h0.x; wA += h0.y; }
                hacc = fmaf(cc, cA, hacc - wA);
            }
        }
    }

    // ---- block reduce ----
    float r0 = warpSum(hacc);
    float r1 = warpSum(pos_sum);
    float r2 = warpSum(neg_sum);
    if (lane == 0) { s0[wid] = r0; s1[wid] = r1; s2[wid] = r2; }
    __syncthreads();                                   // bar3 (last block-wide barrier)

    // ---- warp 0 epilogue: finalize row, counters, and (if last) the mean ----
    if (wid == 0) {
        int lastFlag = 0;
        if (lane == 0) {
            float ps = 0.f, qs = 0.f, ns = 0.f;
#pragma unroll
            for (int w = 0; w < NW; w++) { ps += s0[w]; qs += s1[w]; ns += s2[w]; }
            int n_p = (int)(sHalf[0].x + sHalf[1].x);  // exact integer in fp32
            int n_n = NL - n_p;
            float pos_calib = (n_p > 0) ? qs / (float)n_p : 0.f;
            float neg_calib = (n_n > 0) ? ns / (float)n_n : 0.f;
            long long denom = (long long)n_p * (long long)n_n;
            float hinge;
            if (denom > 0)      hinge = ps / (float)denom;
            else if (n_p > 0)   hinge = pos_calib;
            else if (n_n > 0)   hinge = neg_calib;
            else                hinge = 1.f;
            g_row[row] = hinge + neg_calib + pos_calib;
            __threadfence();
            // 2-level completion counter: <=32-way contention per address
            int slot = row & 31;
            if (atomicAdd(&g_cnt1[slot], 1) == 31) {
                if (atomicAdd(&g_cnt0, 1) == 31) lastFlag = 1;
            }
        }
        // globally-last block: warp 0 computes the deterministic final mean
        if (__shfl_sync(FULL, lastFlag, 0)) {
            __threadfence();   // acquire all g_row writes
            float v = 0.f;
#pragma unroll
            for (int i = 0; i < NB / 32; i++) v += g_row[lane + 32 * i];
            v = warpSum(v);
            g_cnt1[lane] = 0;              // reset for next graph replay
            if (lane == 0) {
                out[0] = v / (float)NB;
                g_cnt0 = 0;
            }
        }
    }
}

extern "C" void kernel_launch(void* const* d_in, const int* in_sizes, int n_in,
                              void* d_out, int out_size) {
    const float* outputs = (const float*)d_in[0];
    const int*   targets = (const int*)d_in[1];
    row_kernel<<<NB, NT>>>(outputs, targets, (float*)d_out);
}

// round 17
// speedup vs baseline: 1.8968x; 1.1317x over previous
#include <cuda_runtime.h>

#define NB 1024    // batch rows
#define NL 512     // labels per row
#define NT 128     // threads per block (one block per row)
#define NW 4       // warps per block
#define KB 256     // histogram bins
#define HB 128     // bins per half-scan
#define LOV (-8.0f)
#define BW  (0.0625f)    // 1/16
#define INVW (16.0f)
#define FULL 0xffffffffu

__device__ float g_row[NB];
__device__ int   g_cnt1[32];   // level-1 counters (32 blocks each)
__device__ int   g_cnt0 = 0;   // level-0 counter (32 slots)

__inline__ __device__ float warpSum(float v) {
#pragma unroll
    for (int o = 16; o; o >>= 1) v += __shfl_xor_sync(FULL, v, o);
    return v;
}

__global__ __launch_bounds__(NT) void row_kernel(const float* __restrict__ outp,
                                                 const int* __restrict__ tgt,
                                                 float* __restrict__ out) {
    __shared__ __align__(16) int    hcnt[KB];    // positive-count histogram
    __shared__ __align__(16) float2 SP[KB];      // per-half inclusive prefix (count, wsum)
    __shared__ float2 sHalf[2];                  // per-half totals (C, W)
    __shared__ float s0[NW], s1[NW], s2[NW];
    __shared__ int amLast;

    const int row  = blockIdx.x;
    const int tid  = threadIdx.x;
    const int lane = tid & 31;
    const int wid  = tid >> 5;

    // ---- issue global loads FIRST (latency hides behind zero + barrier) ----
    const float4 ov = reinterpret_cast<const float4*>(outp + row * NL)[tid];
    const int4   tv = reinterpret_cast<const int4*>(tgt  + row * NL)[tid];

    // ---- zero histogram (128 threads x int2 = 256 bins) ----
    reinterpret_cast<int2*>(hcnt)[tid] = make_int2(0, 0);
    __syncthreads();                                   // bar0

    // ---- classify, calib sums, histogram atomics ----
    float vv[4] = {ov.x, ov.y, ov.z, ov.w};
    int   tt[4] = {tv.x, tv.y, tv.z, tv.w};
    unsigned negmask = 0;
    float pos_sum = 0.f, neg_sum = 0.f;
#pragma unroll
    for (int k = 0; k < 4; k++) {
        float v = vv[k];
        if (tt[k] != 0) {
            pos_sum += fmaxf(1.f - v, 0.f);
            int b = min(max(__float2int_rd((v - LOV) * INVW), 0), KB - 1);
            atomicAdd(&hcnt[b], 1);
        } else {
            neg_sum += fmaxf(1.f + v, 0.f);
            negmask |= 1u << k;
        }
    }
    __syncthreads();                                   // bar1

    // ---- concurrent half-scans: warp r scans bins [r*128, r*128+128) ----
    if (wid < 2) {
        const int r = wid;
        int4 a = reinterpret_cast<const int4*>(hcnt)[r * 32 + lane];  // 4 bins/lane
        int cb[4] = {a.x, a.y, a.z, a.w};
        const int b0 = r * HB + lane * 4;
        const float ctr0 = LOV + ((float)b0 + 0.5f) * BW;
        float rc = 0.f, rw = 0.f;
#pragma unroll
        for (int i = 0; i < 4; i++) {
            float f = (float)cb[i];
            rc += f;
            rw = fmaf(f, ctr0 + (float)i * BW, rw);
        }
        float sc = rc, sw = rw;                         // inclusive scan of lane totals
#pragma unroll
        for (int o = 1; o < 32; o <<= 1) {
            float tc = __shfl_up_sync(FULL, sc, o);
            float tw = __shfl_up_sync(FULL, sw, o);
            if (lane >= o) { sc += tc; sw += tw; }
        }
        float ac = sc - rc, aw = sw - rw;               // exclusive prefix within half
#pragma unroll
        for (int i = 0; i < 4; i++) {
            float f = (float)cb[i];
            ac += f;
            aw = fmaf(f, ctr0 + (float)i * BW, aw);
            SP[b0 + i] = make_float2(ac, aw);
        }
        if (lane == 31) sHalf[r] = make_float2(sc, sw); // half totals
    }
    __syncthreads();                                   // bar2

    // ---- per-negative O(1) lookup: sum relu(cc - p) ~= cc*cntBelow - wsumBelow ----
    const float2 h0 = sHalf[0];                        // broadcast
    float hacc = 0.f;
#pragma unroll
    for (int k = 0; k < 4; k++) {
        if (negmask & (1u << k)) {
            float cc = 1.f + vv[k];
            int m = min(max(__float2int_rd((cc - LOV) * INVW + 0.5f), 0), KB);
            if (m > 0) {
                float2 pw = SP[m - 1];
                float cA = pw.x, wA = pw.y;
                if (m > HB) { cA += h0.x; wA += h0.y; }
                hacc = fmaf(cc, cA, hacc - wA);
            }
        }
    }

    // ---- block reduce ----
    float r0 = warpSum(hacc);
    float r1 = warpSum(pos_sum);
    float r2 = warpSum(neg_sum);
    if (lane == 0) { s0[wid] = r0; s1[wid] = r1; s2[wid] = r2; }
    __syncthreads();                                   // bar3

    if (tid == 0) {
        float ps = 0.f, qs = 0.f, ns = 0.f;
#pragma unroll
        for (int w = 0; w < NW; w++) { ps += s0[w]; qs += s1[w]; ns += s2[w]; }
        int n_p = (int)(sHalf[0].x + sHalf[1].x);      // exact integer in fp32
        int n_n = NL - n_p;
        float pos_calib = (n_p > 0) ? qs / (float)n_p : 0.f;
        float neg_calib = (n_n > 0) ? ns / (float)n_n : 0.f;
        long long denom = (long long)n_p * (long long)n_n;
        float hinge;
        if (denom > 0)      hinge = ps / (float)denom;
        else if (n_p > 0)   hinge = pos_calib;
        else if (n_n > 0)   hinge = neg_calib;
        else                hinge = 1.f;
        g_row[row] = hinge + neg_calib + pos_calib;
        __threadfence();
        // 2-level completion counter: <=32-way contention per address
        amLast = 0;
        int slot = row & 31;
        if (atomicAdd(&g_cnt1[slot], 1) == 31) {
            if (atomicAdd(&g_cnt0, 1) == 31) amLast = 1;
        }
    }
    __syncthreads();                                   // bar4

    // ---- globally-last block: deterministic final mean; reset counters ----
    if (amLast) {
        __threadfence();   // acquire all g_row writes
        float v = 0.f;
#pragma unroll
        for (int i = 0; i < NB / NT; i++) v += g_row[tid + NT * i];
        v = warpSum(v);
        if (lane == 0) s0[wid] = v;
        __syncthreads();
        if (tid < 32) g_cnt1[tid] = 0;     // reset for next graph replay
        if (tid == 0) {
            float t = 0.f;
#pragma unroll
            for (int w = 0; w < NW; w++) t += s0[w];
            out[0] = t / (float)NB;
            g_cnt0 = 0;
        }
    }
}

extern "C" void kernel_launch(void* const* d_in, const int* in_sizes, int n_in,
                              void* d_out, int out_size) {
    const float* outputs = (const float*)d_in[0];
    const int*   targets = (const int*)d_in[1];
    row_kernel<<<NB, NT>>>(outputs, targets, (float*)d_out);
}